// round 1
// baseline (speedup 1.0000x reference)
#include <cuda_runtime.h>
#include <math.h>

#define NN 2048
#define KK 16
#define MM 64

// ---------------- device scratch (no allocations allowed) ----------------
__device__ double g_acc;
__device__ float  g_Ma[KK * KK];
__device__ float  g_Mb[KK * KK];
__device__ float  g_dd[NN * KK];

// ---------------- helpers ----------------
__device__ __forceinline__ float digammaf_(float x) {
    // valid for x > 0; shift to >= 7 then asymptotic series (err < 1e-9 there)
    float r = 0.f;
    #pragma unroll 1
    while (x < 7.f) { r -= 1.f / x; x += 1.f; }
    float inv  = 1.f / x;
    float inv2 = inv * inv;
    return r + logf(x) - 0.5f * inv
         - inv2 * (0.0833333333333f
                 - inv2 * (0.00833333333333f
                 - inv2 * 0.00396825396825f));
}

__device__ __forceinline__ void block_add(double v) {
    #pragma unroll
    for (int o = 16; o; o >>= 1) v += __shfl_down_sync(0xffffffffu, v, o);
    __shared__ double sred[32];
    int lane = threadIdx.x & 31, w = threadIdx.x >> 5;
    if (lane == 0) sred[w] = v;
    __syncthreads();
    if (w == 0) {
        int nw = (blockDim.x + 31) >> 5;
        double t = (lane < nw) ? sred[lane] : 0.0;
        #pragma unroll
        for (int o = 16; o; o >>= 1) t += __shfl_down_sync(0xffffffffu, t, o);
        if (lane == 0) atomicAdd(&g_acc, t);
    }
}

// ---------------- kernel A: K x K beta terms, build Ma/Mb ----------------
__global__ void kA(const float* __restrict__ alphas, const float* __restrict__ betas,
                   const float* __restrict__ ap_, const float* __restrict__ bp_) {
    __shared__ float sSa[KK * KK], sSb[KK * KK];
    int t = threadIdx.x;                 // 256 threads, one per (k,l)
    if (t == 0) g_acc = 0.0;             // re-zero on every launch (graph replay safe)
    float a  = expf(alphas[t]);
    float be = expf(betas[t]);
    float ap = expf(ap_[t]);
    float bp = expf(bp_[t]);
    float dia = digammaf_(ap);
    float dib = digammaf_(bp);
    float dis = digammaf_(ap + bp);
    float Sa = dia - dis, Sb = dib - dis;
    sSa[t] = Sa; sSb[t] = Sb;
    __syncthreads();
    int k = t >> 4, l = t & 15;
    g_Ma[t] = sSa[t] + sSa[l * KK + k];  // Sa + Sa^T
    g_Mb[t] = sSb[t] + sSb[l * KK + k];
    double acc = 0.0;
    if (k <= l) {                        // triu incl diagonal
        acc += (double)((a - 1.f) * Sa + (be - 1.f) * Sb);       // ln p(B)
        float lb = lgammaf(ap) + lgammaf(bp) - lgammaf(ap + bp); // lbeta
        acc += (double)(lb - (ap - 1.f) * dia - (bp - 1.f) * dib
                        + (ap + bp - 2.f) * dis);                // ent_b
    }
    block_add(acc);
}

// ---------------- kernel B: per-node Dirichlet + RBM terms, write dd ----------------
__global__ void kB(const float* __restrict__ mu, const float* __restrict__ w,
                   const float* __restrict__ b, const float* __restrict__ c,
                   const float* __restrict__ attr) {
    int i = blockIdx.x * blockDim.x + threadIdx.x;
    double acc = 0.0;
    if (i < NN) {
        float me[KK];
        float mu0 = 0.f;
        #pragma unroll
        for (int k = 0; k < KK; k++) { me[k] = expf(mu[i * KK + k]); mu0 += me[k]; }
        float dmu0 = digammaf_(mu0);
        float a = 0.f;
        #pragma unroll
        for (int k = 0; k < KK; k++) {
            float d = digammaf_(me[k]);
            g_dd[i * KK + k] = d - dmu0;
            a += lgammaf(me[k]) - (me[k] - 1.f) * d;   // ent_z pieces
        }
        a += (mu0 - (float)KK) * dmu0 - lgammaf(mu0);
        float inv = 1.f / mu0;
        float mn[KK];
        #pragma unroll
        for (int k = 0; k < KK; k++) mn[k] = me[k] * inv;
        float pz = 0.f;
        for (int m = 0; m < MM; m++) {
            float s = 0.f;
            #pragma unroll
            for (int k = 0; k < KK; k++) s += mn[k] * w[k * MM + m];
            pz += attr[i * MM + m] * (s + b[m]);       // (mu_n @ w)*attr + attr@b
        }
        float cz = 0.f;
        #pragma unroll
        for (int k = 0; k < KK; k++) cz += c[k] * mn[k];
        acc = (double)a + (double)pz + (double)cz;
    }
    block_add(acc);
}

// ---------------- kernel C: the heavy pass over all unordered pairs ----------------
__global__ void __launch_bounds__(256) kC(const float* __restrict__ q,
                                          const int* __restrict__ adj) {
    __shared__ float sMa[256], sMb[256], sddI[256], sddJ[256];
    int bid = blockIdx.x;
    // decode lower-triangle tile index: bid = ti*(ti+1)/2 + tj, tj <= ti
    int ti = (int)((sqrtf(8.f * (float)bid + 1.f) - 1.f) * 0.5f);
    while ((ti + 1) * (ti + 2) / 2 <= bid) ti++;
    while (ti * (ti + 1) / 2 > bid) ti--;
    int tj = bid - ti * (ti + 1) / 2;

    int t = threadIdx.x;
    int r = t >> 4, cc = t & 15;
    sMa[t]  = g_Ma[t];
    sMb[t]  = g_Mb[t];
    sddI[t] = g_dd[(ti * 16 + r) * KK + cc];
    sddJ[t] = g_dd[(tj * 16 + r) * KK + cc];
    __syncthreads();

    int i = ti * 16 + r;      // row (larger index)
    int j = tj * 16 + cc;     // col

    const float4* q4 = (const float4*)q;
    size_t bij = ((size_t)i * NN + j) * 4;   // float4 index of q[i,j,:]
    size_t bji = ((size_t)j * NN + i) * 4;   // float4 index of q[j,i,:]

    float eij[KK], eji[KK];
    float Zi = 0.f, Zj = 0.f, dxi = 0.f, dxj = 0.f, sdi = 0.f, sdj = 0.f;

    #pragma unroll
    for (int p = 0; p < 4; p++) {
        float4 v = q4[bij + p];
        float xs[4] = {v.x, v.y, v.z, v.w};
        #pragma unroll
        for (int u = 0; u < 4; u++) {
            int k = p * 4 + u;
            float e = __expf(xs[u]);
            eij[k] = e;
            Zi  += e;
            dxi += e * xs[u];
            sdi += e * sddI[r * 16 + k];
        }
    }
    #pragma unroll
    for (int p = 0; p < 4; p++) {
        float4 v = q4[bji + p];
        float xs[4] = {v.x, v.y, v.z, v.w};
        #pragma unroll
        for (int u = 0; u < 4; u++) {
            int k = p * 4 + u;
            float e = __expf(xs[u]);
            eji[k] = e;
            Zj  += e;
            dxj += e * xs[u];
            sdj += e * sddJ[cc * 16 + k];
        }
    }

    int av = adj[(size_t)i * NN + j];           // lower-triangle adjacency
    const float* Mp = av ? sMa : sMb;
    float tsum = 0.f;
    #pragma unroll
    for (int k = 0; k < KK; k++) {
        float rd = 0.f;
        #pragma unroll
        for (int l = 0; l < KK; l++) rd += Mp[k * 16 + l] * eij[l];
        tsum += eji[k] * rd;
    }

    float rZi = __fdividef(1.f, Zi);
    float rZj = __fdividef(1.f, Zj);
    // S (both orientations) - q log q (both) + pair bilinear
    float contrib = sdi * rZi + sdj * rZj
                  - (dxi * rZi - __logf(Zi))
                  - (dxj * rZj - __logf(Zj))
                  + tsum * rZi * rZj;

    double acc = (i > j) ? (double)contrib : 0.0;
    block_add(acc);
}

// ---------------- kernel D: finalize ----------------
__global__ void kD(float* out) { out[0] = (float)(-g_acc); }

// ---------------- launch ----------------
extern "C" void kernel_launch(void* const* d_in, const int* in_sizes, int n_in,
                              void* d_out, int out_size) {
    const float* alphas = (const float*)d_in[0];
    const float* betas  = (const float*)d_in[1];
    const float* ap     = (const float*)d_in[2];
    const float* bp     = (const float*)d_in[3];
    const float* mu     = (const float*)d_in[4];
    const float* q      = (const float*)d_in[5];
    const float* w      = (const float*)d_in[6];
    const float* b      = (const float*)d_in[7];
    const float* c      = (const float*)d_in[8];
    const float* attr   = (const float*)d_in[9];
    const int*   adj    = (const int*)d_in[10];

    kA<<<1, 256>>>(alphas, betas, ap, bp);
    kB<<<NN / 256, 256>>>(mu, w, b, c, attr);
    kC<<<(128 * 129) / 2, 256>>>(q, adj);
    kD<<<1, 1>>>((float*)d_out);
}

// round 2
// speedup vs baseline: 1.0573x; 1.0573x over previous
#include <cuda_runtime.h>
#include <math.h>

#define NN 2048
#define KK 16
#define MM 64
#define VS 20          // padded float-stride per 16-float vector slot (80B)

// ---------------- device scratch (no allocations allowed) ----------------
__device__ double g_acc;
__device__ float  g_Ma[KK * KK];
__device__ float  g_Mb[KK * KK];
__device__ float  g_dd[NN * KK];

// ---------------- f32x2 packed helpers ----------------
__device__ __forceinline__ unsigned long long pk2(float lo, float hi) {
    unsigned long long r;
    asm("mov.b64 %0, {%1, %2};" : "=l"(r) : "f"(lo), "f"(hi));
    return r;
}
__device__ __forceinline__ void upk2(unsigned long long v, float& lo, float& hi) {
    asm("mov.b64 {%0, %1}, %2;" : "=f"(lo), "=f"(hi) : "l"(v));
}
__device__ __forceinline__ unsigned long long fma2_(unsigned long long a,
                                                    unsigned long long b,
                                                    unsigned long long c) {
    unsigned long long d;
    asm("fma.rn.f32x2 %0, %1, %2, %3;" : "=l"(d) : "l"(a), "l"(b), "l"(c));
    return d;
}
__device__ __forceinline__ unsigned long long add2_(unsigned long long a,
                                                    unsigned long long b) {
    unsigned long long d;
    asm("add.rn.f32x2 %0, %1, %2;" : "=l"(d) : "l"(a), "l"(b));
    return d;
}
__device__ __forceinline__ float hsum2(unsigned long long v) {
    float lo, hi; upk2(v, lo, hi); return lo + hi;
}

// ---------------- helpers ----------------
__device__ __forceinline__ float digammaf_(float x) {
    float r = 0.f;
    #pragma unroll 1
    while (x < 7.f) { r -= 1.f / x; x += 1.f; }
    float inv  = 1.f / x;
    float inv2 = inv * inv;
    return r + logf(x) - 0.5f * inv
         - inv2 * (0.0833333333333f
                 - inv2 * (0.00833333333333f
                 - inv2 * 0.00396825396825f));
}

__device__ __forceinline__ void block_add(double v) {
    #pragma unroll
    for (int o = 16; o; o >>= 1) v += __shfl_down_sync(0xffffffffu, v, o);
    __shared__ double sred[32];
    int lane = threadIdx.x & 31, w = threadIdx.x >> 5;
    if (lane == 0) sred[w] = v;
    __syncthreads();
    if (w == 0) {
        int nw = (blockDim.x + 31) >> 5;
        double t = (lane < nw) ? sred[lane] : 0.0;
        #pragma unroll
        for (int o = 16; o; o >>= 1) t += __shfl_down_sync(0xffffffffu, t, o);
        if (lane == 0) atomicAdd(&g_acc, t);
    }
}

// ---------------- kernel A: K x K beta terms, build Ma/Mb ----------------
__global__ void kA(const float* __restrict__ alphas, const float* __restrict__ betas,
                   const float* __restrict__ ap_, const float* __restrict__ bp_) {
    __shared__ float sSa[KK * KK], sSb[KK * KK];
    int t = threadIdx.x;
    if (t == 0) g_acc = 0.0;
    float a  = expf(alphas[t]);
    float be = expf(betas[t]);
    float ap = expf(ap_[t]);
    float bp = expf(bp_[t]);
    float dia = digammaf_(ap);
    float dib = digammaf_(bp);
    float dis = digammaf_(ap + bp);
    float Sa = dia - dis, Sb = dib - dis;
    sSa[t] = Sa; sSb[t] = Sb;
    __syncthreads();
    int k = t >> 4, l = t & 15;
    g_Ma[t] = sSa[t] + sSa[l * KK + k];
    g_Mb[t] = sSb[t] + sSb[l * KK + k];
    double acc = 0.0;
    if (k <= l) {
        acc += (double)((a - 1.f) * Sa + (be - 1.f) * Sb);
        float lb = lgammaf(ap) + lgammaf(bp) - lgammaf(ap + bp);
        acc += (double)(lb - (ap - 1.f) * dia - (bp - 1.f) * dib
                        + (ap + bp - 2.f) * dis);
    }
    block_add(acc);
}

// ---------------- kernel B: per-node Dirichlet + RBM terms, write dd ----------------
__global__ void kB(const float* __restrict__ mu, const float* __restrict__ w,
                   const float* __restrict__ b, const float* __restrict__ c,
                   const float* __restrict__ attr) {
    int i = blockIdx.x * blockDim.x + threadIdx.x;
    double acc = 0.0;
    if (i < NN) {
        float me[KK];
        float mu0 = 0.f;
        #pragma unroll
        for (int k = 0; k < KK; k++) { me[k] = expf(mu[i * KK + k]); mu0 += me[k]; }
        float dmu0 = digammaf_(mu0);
        float a = 0.f;
        #pragma unroll
        for (int k = 0; k < KK; k++) {
            float d = digammaf_(me[k]);
            g_dd[i * KK + k] = d - dmu0;
            a += lgammaf(me[k]) - (me[k] - 1.f) * d;
        }
        a += (mu0 - (float)KK) * dmu0 - lgammaf(mu0);
        float inv = 1.f / mu0;
        float mn[KK];
        #pragma unroll
        for (int k = 0; k < KK; k++) mn[k] = me[k] * inv;
        float pz = 0.f;
        for (int m = 0; m < MM; m++) {
            float s = 0.f;
            #pragma unroll
            for (int k = 0; k < KK; k++) s += mn[k] * w[k * MM + m];
            pz += attr[i * MM + m] * (s + b[m]);
        }
        float cz = 0.f;
        #pragma unroll
        for (int k = 0; k < KK; k++) cz += c[k] * mn[k];
        acc = (double)a + (double)pz + (double)cz;
    }
    block_add(acc);
}

// ---------------- kernel C: heavy pass over all unordered pairs ----------------
__global__ void __launch_bounds__(256) kC(const float* __restrict__ q,
                                          const int* __restrict__ adj) {
    __shared__ float sM[520];            // Ma @0, Mb @260 (1040B offset: bank-disjoint)
    __shared__ float sddI[256], sddJ[256];
    __shared__ float sQij[256 * VS];     // q[i,j,:] vectors, slot (r*16+cc), 80B stride
    __shared__ float sQji[256 * VS];     // q[j,i,:] vectors, stored transposed to slot (r*16+cc)

    int bid = blockIdx.x;
    int ti = (int)((sqrtf(8.f * (float)bid + 1.f) - 1.f) * 0.5f);
    while ((ti + 1) * (ti + 2) / 2 <= bid) ti++;
    while (ti * (ti + 1) / 2 > bid) ti--;
    int tj = bid - ti * (ti + 1) / 2;

    int t = threadIdx.x;
    sM[t]       = g_Ma[t];
    sM[260 + t] = g_Mb[t];
    sddI[t] = g_dd[ti * 256 + t];        // rows ti*16..+15 contiguous
    sddJ[t] = g_dd[tj * 256 + t];

    // Coalesced staging of both 16x16x16 tiles (1024 float4 each)
    const float4* q4 = (const float4*)q;
    #pragma unroll
    for (int m = 0; m < 4; m++) {
        int idx = m * 256 + t;           // 0..1023
        int row = idx >> 6;              // local row within tile (0..15)
        int rem = idx & 63;              // float4 within 1KB row
        int vec = rem >> 2, p = rem & 3;
        float4 a = q4[((size_t)(ti * 16 + row) * NN + tj * 16) * 4 + rem];
        ((float4*)(sQij + (row * 16 + vec) * VS))[p] = a;   // slot (i_loc, j_loc)
        float4 bb = q4[((size_t)(tj * 16 + row) * NN + ti * 16) * 4 + rem];
        ((float4*)(sQji + (vec * 16 + row) * VS))[p] = bb;  // transpose: slot (i_loc, j_loc)
    }
    __syncthreads();

    int r = t >> 4, cc = t & 15;         // local i, local j
    int i = ti * 16 + r, j = tj * 16 + cc;

    const float4* vij = (const float4*)(sQij + (r * 16 + cc) * VS);
    const float4* vji = (const float4*)(sQji + (r * 16 + cc) * VS);
    const float4* dI4 = (const float4*)(sddI + r * 16);
    const float4* dJ4 = (const float4*)(sddJ + cc * 16);

    unsigned long long pe_ij[8], pe_ji[8];
    unsigned long long Z2i = pk2(0.f, 0.f), Z2j = Z2i;
    unsigned long long dx2i = Z2i, dx2j = Z2i, sd2i = Z2i, sd2j = Z2i;

    #pragma unroll
    for (int p = 0; p < 4; p++) {
        float4 v = vij[p];
        float e0 = __expf(v.x), e1 = __expf(v.y), e2 = __expf(v.z), e3 = __expf(v.w);
        unsigned long long pa = pk2(e0, e1), pb = pk2(e2, e3);
        pe_ij[2 * p] = pa; pe_ij[2 * p + 1] = pb;
        Z2i  = add2_(Z2i, pa);                 Z2i  = add2_(Z2i, pb);
        dx2i = fma2_(pa, pk2(v.x, v.y), dx2i); dx2i = fma2_(pb, pk2(v.z, v.w), dx2i);
        float4 d = dI4[p];
        sd2i = fma2_(pa, pk2(d.x, d.y), sd2i); sd2i = fma2_(pb, pk2(d.z, d.w), sd2i);
    }
    #pragma unroll
    for (int p = 0; p < 4; p++) {
        float4 v = vji[p];
        float e0 = __expf(v.x), e1 = __expf(v.y), e2 = __expf(v.z), e3 = __expf(v.w);
        unsigned long long pa = pk2(e0, e1), pb = pk2(e2, e3);
        pe_ji[2 * p] = pa; pe_ji[2 * p + 1] = pb;
        Z2j  = add2_(Z2j, pa);                 Z2j  = add2_(Z2j, pb);
        dx2j = fma2_(pa, pk2(v.x, v.y), dx2j); dx2j = fma2_(pb, pk2(v.z, v.w), dx2j);
        float4 d = dJ4[p];
        sd2j = fma2_(pa, pk2(d.x, d.y), sd2j); sd2j = fma2_(pb, pk2(d.z, d.w), sd2j);
    }

    // bilinear: e_ji^T M e_ij, M = Ma (edge) or Mb (non-edge)
    int av = adj[(size_t)i * NN + j];
    const float4* M4 = (const float4*)(sM + (av ? 0 : 260));
    unsigned long long ts2 = pk2(0.f, 0.f);
    #pragma unroll
    for (int k2 = 0; k2 < 8; k2++) {
        unsigned long long ra2 = pk2(0.f, 0.f), rb2 = ra2;
        #pragma unroll
        for (int l4 = 0; l4 < 4; l4++) {
            float4 ma = M4[(2 * k2) * 4 + l4];
            ra2 = fma2_(pk2(ma.x, ma.y), pe_ij[2 * l4], ra2);
            ra2 = fma2_(pk2(ma.z, ma.w), pe_ij[2 * l4 + 1], ra2);
            float4 mb = M4[(2 * k2 + 1) * 4 + l4];
            rb2 = fma2_(pk2(mb.x, mb.y), pe_ij[2 * l4], rb2);
            rb2 = fma2_(pk2(mb.z, mb.w), pe_ij[2 * l4 + 1], rb2);
        }
        ts2 = fma2_(pe_ji[k2], pk2(hsum2(ra2), hsum2(rb2)), ts2);
    }

    float Zi = hsum2(Z2i), Zj = hsum2(Z2j);
    float dxi = hsum2(dx2i), dxj = hsum2(dx2j);
    float sdi = hsum2(sd2i), sdj = hsum2(sd2j);
    float tsum = hsum2(ts2);

    float rZi = __fdividef(1.f, Zi);
    float rZj = __fdividef(1.f, Zj);
    float contrib = sdi * rZi + sdj * rZj
                  - (dxi * rZi - __logf(Zi))
                  - (dxj * rZj - __logf(Zj))
                  + tsum * rZi * rZj;

    double acc = (i > j) ? (double)contrib : 0.0;
    block_add(acc);
}

// ---------------- kernel D: finalize ----------------
__global__ void kD(float* out) { out[0] = (float)(-g_acc); }

// ---------------- launch ----------------
extern "C" void kernel_launch(void* const* d_in, const int* in_sizes, int n_in,
                              void* d_out, int out_size) {
    const float* alphas = (const float*)d_in[0];
    const float* betas  = (const float*)d_in[1];
    const float* ap     = (const float*)d_in[2];
    const float* bp     = (const float*)d_in[3];
    const float* mu     = (const float*)d_in[4];
    const float* q      = (const float*)d_in[5];
    const float* w      = (const float*)d_in[6];
    const float* b      = (const float*)d_in[7];
    const float* c      = (const float*)d_in[8];
    const float* attr   = (const float*)d_in[9];
    const int*   adj    = (const int*)d_in[10];

    kA<<<1, 256>>>(alphas, betas, ap, bp);
    kB<<<NN / 256, 256>>>(mu, w, b, c, attr);
    kC<<<(128 * 129) / 2, 256>>>(q, adj);
    kD<<<1, 1>>>((float*)d_out);
}